// round 9
// baseline (speedup 1.0000x reference)
#include <cuda_runtime.h>
#include <cuda_fp16.h>
#include <math.h>
#include <stdint.h>

// Fixed problem shapes
#define EE 400000
#define NN 50000
#define RR 6
#define HH 128
#define DD 256
#define NSTRIP (EE / 64)

// Scratch
__device__ __half g_t0h[(size_t)EE * DD];
__device__ __half g_t1h[(size_t)EE * DD];
__device__ __half g_wupT[(size_t)DD * HH];     // w_up^T [256][128]
__device__ __half g_wT [(size_t)3 * DD * DD];  // Ws^T 3 x [256][256]

// ------------------------------------------------------------------
__device__ __forceinline__ uint32_t smem_u32(const void* p) {
    uint32_t a;
    asm("{ .reg .u64 t; cvta.to.shared.u64 t, %1; cvt.u32.u64 %0, t; }"
        : "=r"(a) : "l"(p));
    return a;
}
__device__ __forceinline__ void ldsm4(uint32_t& r0, uint32_t& r1,
                                      uint32_t& r2, uint32_t& r3,
                                      uint32_t addr) {
    asm volatile("ldmatrix.sync.aligned.m8n8.x4.shared.b16 {%0,%1,%2,%3}, [%4];"
                 : "=r"(r0), "=r"(r1), "=r"(r2), "=r"(r3) : "r"(addr));
}
__device__ __forceinline__ void mma_f16(float* c, const uint32_t* a,
                                        const uint32_t* b) {
    asm volatile(
        "mma.sync.aligned.m16n8k16.row.col.f32.f16.f16.f32 "
        "{%0,%1,%2,%3}, {%4,%5,%6,%7}, {%8,%9}, {%0,%1,%2,%3};"
        : "+f"(c[0]), "+f"(c[1]), "+f"(c[2]), "+f"(c[3])
        : "r"(a[0]), "r"(a[1]), "r"(a[2]), "r"(a[3]), "r"(b[0]), "r"(b[1]));
}
__device__ __forceinline__ float silu(float v) {
    return __fdividef(v, 1.f + __expf(-v));
}
#define CP16(dst, src) \
    asm volatile("cp.async.cg.shared.global [%0], [%1], 16;" :: "r"(dst), "l"(src))
#define CPCOMMIT() asm volatile("cp.async.commit_group;" ::: "memory")
#define CPWAIT(n)  asm volatile("cp.async.wait_group %0;" :: "n"(n) : "memory")

// ------------------------------------------------------------------
__global__ void zero_kernel(float4* p, int n4) {
    int i = blockIdx.x * blockDim.x + threadIdx.x;
    if (i < n4) p[i] = make_float4(0.f, 0.f, 0.f, 0.f);
}
__global__ void convert_weights(const float* __restrict__ wup,
                                const float* __restrict__ Ws,
                                __half* __restrict__ wupT,
                                __half* __restrict__ wT) {
    int i = blockIdx.x * blockDim.x + threadIdx.x;
    if (i < DD * HH) {
        int n = i / HH, k = i % HH;
        wupT[i] = __float2half(wup[k * DD + n]);
        return;
    }
    i -= DD * HH;
    if (i < 3 * DD * DD) {
        int l = i / (DD * DD), r = i % (DD * DD);
        int n = r / DD, k = r % DD;
        wT[i] = __float2half(Ws[(size_t)l * DD * DD + k * DD + n]);
    }
}

// ==================================================================
// k_first: persistent. W_up resident in SMEM. Per strip: stage x fp32,
// compute h = (rbf@w_rbf)*x (fp32 scatter into x_spe, fp16 into A-strip),
// MMA K=128 -> t0 fp16 (no activation).
// SMEM: W 256x136h @0 (69632B) | xstage 2 x 64x132 f32 @69632 (67584B)
//       | astrip 2 x 64x136h @137216 (34816B)  total 172032
#define F_WSTR 136
#define F_XSTR 132
#define F_ASTR 136
#define F_SMEM 172032

__global__ __launch_bounds__(512, 1)
void k_first(const float* __restrict__ x, const float* __restrict__ rbf,
             const int* __restrict__ idx, const float* __restrict__ w_rbf,
             const __half* __restrict__ wupT,
             float* __restrict__ xspe, __half* __restrict__ t0)
{
    extern __shared__ char smem[];
    __half* Wsm = (__half*)smem;
    float*  xst = (float*)(smem + 69632);
    __half* ast = (__half*)(smem + 137216);
    const uint32_t sbW = smem_u32(Wsm);
    const uint32_t sbX = smem_u32(xst);
    const uint32_t sbA = smem_u32(ast);

    const int tid = threadIdx.x;
    const int warp = tid >> 5, lane = tid & 31;
    const int wm = warp & 1, wn = warp >> 1;
    const int g = lane >> 2, t = lane & 3;

    // prologue: issue x strip blockIdx.x into stage 0
    {
        const float* src = x + (size_t)blockIdx.x * 64 * HH;
#pragma unroll
        for (int it = 0; it < 4; it++) {
            int q = tid + it * 512;
            int row = q >> 5, seg = q & 31;
            CP16(sbX + (uint32_t)(row * F_XSTR + seg * 4) * 4,
                 src + (size_t)row * HH + seg * 4);
        }
        CPCOMMIT();
    }
    // W_up^T resident load (256x128 halves)
#pragma unroll
    for (int it = 0; it < 8; it++) {
        int q = tid + it * 512;
        int row = q >> 4, seg = q & 15;
        *(float4*)(Wsm + row * F_WSTR + seg * 8) =
            __ldg((const float4*)(wupT + (size_t)row * HH + seg * 8));
    }

    const uint32_t aLane = (uint32_t)((lane & 15) * F_ASTR + ((lane & 16) ? 8 : 0)) * 2;
    const uint32_t bBase = sbW +
        (uint32_t)((wn * 32 + (lane & 7) + ((lane & 16) ? 8 : 0)) * F_WSTR +
                   ((lane & 8) ? 8 : 0)) * 2;

    int b = 0;
    for (int s = blockIdx.x; s < NSTRIP; s += gridDim.x) {
        int nx = s + gridDim.x;
        if (nx < NSTRIP) {
            const float* src = x + (size_t)nx * 64 * HH;
            uint32_t dst = sbX + (uint32_t)((b ^ 1) * 8448) * 4;
#pragma unroll
            for (int it = 0; it < 4; it++) {
                int q = tid + it * 512;
                int row = q >> 5, seg = q & 31;
                CP16(dst + (uint32_t)(row * F_XSTR + seg * 4) * 4,
                     src + (size_t)row * HH + seg * 4);
            }
            CPCOMMIT();
            CPWAIT(1);
        } else {
            CPWAIT(0);
        }
        __syncthreads();

        const size_t e0 = (size_t)s * 64;
        // ---- h phase: row r = tid/8, cols (tid%8)*16..+15 ----
        {
            const int r = tid >> 3;
            const int cb = (tid & 7) << 4;
            const float* xrow = xst + b * 8448 + r * F_XSTR;
            const float* rb = rbf + (e0 + r) * RR;
            float r0 = __ldg(rb + 0), r1 = __ldg(rb + 1), r2 = __ldg(rb + 2);
            float r3 = __ldg(rb + 3), r4 = __ldg(rb + 4), r5 = __ldg(rb + 5);
            const int node = __ldg(idx + e0 + r);
            __half* arow = ast + b * 8704 + r * F_ASTR;
            float* xd = xspe + (size_t)node * HH;
#pragma unroll
            for (int cc = 0; cc < 16; cc += 4) {
                int c = cb + cc;
                float4 xv = *reinterpret_cast<const float4*>(xrow + c);
                float4 w0 = __ldg((const float4*)(w_rbf + 0 * HH + c));
                float4 w1 = __ldg((const float4*)(w_rbf + 1 * HH + c));
                float4 w2 = __ldg((const float4*)(w_rbf + 2 * HH + c));
                float4 w3 = __ldg((const float4*)(w_rbf + 3 * HH + c));
                float4 w4 = __ldg((const float4*)(w_rbf + 4 * HH + c));
                float4 w5 = __ldg((const float4*)(w_rbf + 5 * HH + c));
                float4 h;
                h.x = (r0*w0.x + r1*w1.x + r2*w2.x + r3*w3.x + r4*w4.x + r5*w5.x) * xv.x;
                h.y = (r0*w0.y + r1*w1.y + r2*w2.y + r3*w3.y + r4*w4.y + r5*w5.y) * xv.y;
                h.z = (r0*w0.z + r1*w1.z + r2*w2.z + r3*w3.z + r4*w4.z + r5*w5.z) * xv.z;
                h.w = (r0*w0.w + r1*w1.w + r2*w2.w + r3*w3.w + r4*w4.w + r5*w5.w) * xv.w;
                *reinterpret_cast<__half2*>(arow + c)     = __floats2half2_rn(h.x, h.y);
                *reinterpret_cast<__half2*>(arow + c + 2) = __floats2half2_rn(h.z, h.w);
                atomicAdd(xd + c + 0, h.x);
                atomicAdd(xd + c + 1, h.y);
                atomicAdd(xd + c + 2, h.z);
                atomicAdd(xd + c + 3, h.w);
            }
        }
        __syncthreads();

        // ---- MMA: 64x256 = A(64x128) @ W^T ----
        const uint32_t aBase = sbA + (uint32_t)(b * 8704) * 2 + aLane;
        float acc[2][4][4];
#pragma unroll
        for (int i = 0; i < 2; i++)
#pragma unroll
            for (int j = 0; j < 4; j++)
#pragma unroll
                for (int q = 0; q < 4; q++) acc[i][j][q] = 0.f;
#pragma unroll
        for (int ks = 0; ks < 8; ks++) {
            uint32_t af[2][4], bf[4][2];
#pragma unroll
            for (int mf = 0; mf < 2; mf++)
                ldsm4(af[mf][0], af[mf][1], af[mf][2], af[mf][3],
                      aBase + (uint32_t)((wm * 32 + mf * 16) * F_ASTR + ks * 16) * 2);
#pragma unroll
            for (int np = 0; np < 2; np++) {
                uint32_t d0, d1, d2, d3;
                ldsm4(d0, d1, d2, d3,
                      bBase + (uint32_t)(np * 16 * F_WSTR + ks * 16) * 2);
                bf[2 * np][0] = d0;     bf[2 * np][1] = d1;
                bf[2 * np + 1][0] = d2; bf[2 * np + 1][1] = d3;
            }
#pragma unroll
            for (int mf = 0; mf < 2; mf++)
#pragma unroll
                for (int nf = 0; nf < 4; nf++)
                    mma_f16(acc[mf][nf], af[mf], bf[nf]);
        }
        // epilogue: raw store t0 fp16
#pragma unroll
        for (int mf = 0; mf < 2; mf++) {
#pragma unroll
            for (int nf = 0; nf < 4; nf++) {
                int r0 = wm * 32 + mf * 16 + g;
                int cc = wn * 32 + nf * 8 + 2 * t;
                *reinterpret_cast<__half2*>(t0 + (e0 + r0) * DD + cc) =
                    __floats2half2_rn(acc[mf][nf][0], acc[mf][nf][1]);
                *reinterpret_cast<__half2*>(t0 + (e0 + r0 + 8) * DD + cc) =
                    __floats2half2_rn(acc[mf][nf][2], acc[mf][nf][3]);
            }
        }
        __syncthreads();
        b ^= 1;
    }
}

// ==================================================================
// layer_k: persistent. One 256x256 weight resident in SMEM.
// Per strip: cp.async t-strip (fp16, double buffered), MMA K=256, epilogue.
// SMEM: W 256x264h @0 (135168B) | astrip 2 x 64x264h @135168 (67584B)
//       | red 64x8 f32 @202752 (2048B)  total 204800
#define M_WSTR 264
#define M_ASTR 264
#define M_SMEM 204800

template<bool LAST>
__global__ __launch_bounds__(512, 1)
void layer_k(const __half* __restrict__ tin, const __half* __restrict__ WT,
             const float* __restrict__ bias, const float* __restrict__ wout,
             __half* __restrict__ tout, float* __restrict__ out1)
{
    extern __shared__ char smem[];
    __half* Wsm = (__half*)smem;
    __half* ast = (__half*)(smem + 135168);
    float* red  = (float*)(smem + 202752);
    const uint32_t sbW = smem_u32(Wsm);
    const uint32_t sbA = smem_u32(ast);

    const int tid = threadIdx.x;
    const int warp = tid >> 5, lane = tid & 31;
    const int wm = warp & 1, wn = warp >> 1;
    const int g = lane >> 2, t = lane & 3;

    // prologue: issue strip blockIdx.x into stage 0
    {
        const __half* src = tin + (size_t)blockIdx.x * 64 * DD;
#pragma unroll
        for (int it = 0; it < 4; it++) {
            int q = tid + it * 512;
            int row = q >> 5, seg = q & 31;
            CP16(sbA + (uint32_t)(row * M_ASTR + seg * 8) * 2,
                 src + (size_t)row * DD + seg * 8);
        }
        CPCOMMIT();
    }
    // W resident load (256x256 halves)
#pragma unroll
    for (int it = 0; it < 16; it++) {
        int q = tid + it * 512;
        int row = q >> 5, seg = q & 31;
        *(float4*)(Wsm + row * M_WSTR + seg * 8) =
            __ldg((const float4*)(WT + (size_t)row * DD + seg * 8));
    }

    const uint32_t aLane = (uint32_t)((lane & 15) * M_ASTR + ((lane & 16) ? 8 : 0)) * 2;
    const uint32_t bBase = sbW +
        (uint32_t)((wn * 32 + (lane & 7) + ((lane & 16) ? 8 : 0)) * M_WSTR +
                   ((lane & 8) ? 8 : 0)) * 2;

    int b = 0;
    for (int s = blockIdx.x; s < NSTRIP; s += gridDim.x) {
        int nx = s + gridDim.x;
        if (nx < NSTRIP) {
            const __half* src = tin + (size_t)nx * 64 * DD;
            uint32_t dst = sbA + (uint32_t)((b ^ 1) * 16896) * 2;
#pragma unroll
            for (int it = 0; it < 4; it++) {
                int q = tid + it * 512;
                int row = q >> 5, seg = q & 31;
                CP16(dst + (uint32_t)(row * M_ASTR + seg * 8) * 2,
                     src + (size_t)row * DD + seg * 8);
            }
            CPCOMMIT();
            CPWAIT(1);
        } else {
            CPWAIT(0);
        }
        __syncthreads();

        const uint32_t aBase = sbA + (uint32_t)(b * 16896) * 2 + aLane;
        float acc[2][4][4];
#pragma unroll
        for (int i = 0; i < 2; i++)
#pragma unroll
            for (int j = 0; j < 4; j++)
#pragma unroll
                for (int q = 0; q < 4; q++) acc[i][j][q] = 0.f;
#pragma unroll
        for (int ks = 0; ks < 16; ks++) {
            uint32_t af[2][4], bf[4][2];
#pragma unroll
            for (int mf = 0; mf < 2; mf++)
                ldsm4(af[mf][0], af[mf][1], af[mf][2], af[mf][3],
                      aBase + (uint32_t)((wm * 32 + mf * 16) * M_ASTR + ks * 16) * 2);
#pragma unroll
            for (int np = 0; np < 2; np++) {
                uint32_t d0, d1, d2, d3;
                ldsm4(d0, d1, d2, d3,
                      bBase + (uint32_t)(np * 16 * M_WSTR + ks * 16) * 2);
                bf[2 * np][0] = d0;     bf[2 * np][1] = d1;
                bf[2 * np + 1][0] = d2; bf[2 * np + 1][1] = d3;
            }
#pragma unroll
            for (int mf = 0; mf < 2; mf++)
#pragma unroll
                for (int nf = 0; nf < 4; nf++)
                    mma_f16(acc[mf][nf], af[mf], bf[nf]);
        }

        const size_t e0 = (size_t)s * 64;
        if (!LAST) {
#pragma unroll
            for (int mf = 0; mf < 2; mf++) {
#pragma unroll
                for (int nf = 0; nf < 4; nf++) {
                    int r0 = wm * 32 + mf * 16 + g;
                    int cc = wn * 32 + nf * 8 + 2 * t;
                    float b0 = __ldg(bias + cc), b1 = __ldg(bias + cc + 1);
                    float v0 = silu(acc[mf][nf][0] + b0);
                    float v1 = silu(acc[mf][nf][1] + b1);
                    float v2 = silu(acc[mf][nf][2] + b0);
                    float v3 = silu(acc[mf][nf][3] + b1);
                    *reinterpret_cast<__half2*>(tout + (e0 + r0) * DD + cc) =
                        __floats2half2_rn(v0, v1);
                    *reinterpret_cast<__half2*>(tout + (e0 + r0 + 8) * DD + cc) =
                        __floats2half2_rn(v2, v3);
                }
            }
            __syncthreads();
        } else {
            float s0[2] = {0.f, 0.f}, s1[2] = {0.f, 0.f};
#pragma unroll
            for (int mf = 0; mf < 2; mf++) {
#pragma unroll
                for (int nf = 0; nf < 4; nf++) {
                    int cc = wn * 32 + nf * 8 + 2 * t;
                    float b0 = __ldg(bias + cc), b1 = __ldg(bias + cc + 1);
                    float w0 = __ldg(wout + cc), w1 = __ldg(wout + cc + 1);
                    s0[mf] += silu(acc[mf][nf][0] + b0) * w0
                            + silu(acc[mf][nf][1] + b1) * w1;
                    s1[mf] += silu(acc[mf][nf][2] + b0) * w0
                            + silu(acc[mf][nf][3] + b1) * w1;
                }
            }
#pragma unroll
            for (int mf = 0; mf < 2; mf++) {
                s0[mf] += __shfl_xor_sync(0xffffffffu, s0[mf], 1);
                s0[mf] += __shfl_xor_sync(0xffffffffu, s0[mf], 2);
                s1[mf] += __shfl_xor_sync(0xffffffffu, s1[mf], 1);
                s1[mf] += __shfl_xor_sync(0xffffffffu, s1[mf], 2);
            }
            if (t == 0) {
#pragma unroll
                for (int mf = 0; mf < 2; mf++) {
                    int rl = wm * 32 + mf * 16 + g;
                    red[rl * 8 + wn] = s0[mf];
                    red[(rl + 8) * 8 + wn] = s1[mf];
                }
            }
            __syncthreads();
            if (tid < 64) {
                float s2 = 0.f;
#pragma unroll
                for (int j = 0; j < 8; j++) s2 += red[tid * 8 + j];
                out1[e0 + tid] = s2;
            }
            __syncthreads();
        }
        b ^= 1;
    }
}

// ------------------------------------------------------------------
extern "C" void kernel_launch(void* const* d_in, const int* in_sizes, int n_in,
                              void* d_out, int out_size) {
    const float* x     = (const float*)d_in[0];
    const float* rbf   = (const float*)d_in[1];
    const int*   idx   = (const int*)  d_in[2];
    const float* w_rbf = (const float*)d_in[3];
    const float* w_up  = (const float*)d_in[4];
    const float* Ws    = (const float*)d_in[5];
    const float* bs    = (const float*)d_in[6];
    const float* w_out = (const float*)d_in[7];

    float* out_f = (float*)d_out;
    float* xspe  = out_f;                         // [N,128]
    float* out1  = out_f + (size_t)NN * HH;       // [E]

    __half *pt0, *pt1, *pwupT, *pwT;
    cudaGetSymbolAddress((void**)&pt0,   g_t0h);
    cudaGetSymbolAddress((void**)&pt1,   g_t1h);
    cudaGetSymbolAddress((void**)&pwupT, g_wupT);
    cudaGetSymbolAddress((void**)&pwT,   g_wT);

    int dev = 0, nsm = 148;
    cudaGetDevice(&dev);
    cudaDeviceGetAttribute(&nsm, cudaDevAttrMultiProcessorCount, dev);

    cudaFuncSetAttribute(k_first,
                         cudaFuncAttributeMaxDynamicSharedMemorySize, F_SMEM);
    cudaFuncSetAttribute(layer_k<false>,
                         cudaFuncAttributeMaxDynamicSharedMemorySize, M_SMEM);
    cudaFuncSetAttribute(layer_k<true>,
                         cudaFuncAttributeMaxDynamicSharedMemorySize, M_SMEM);

    // 0) transpose + convert weights to fp16
    {
        int tot = DD * HH + 3 * DD * DD;
        convert_weights<<<(tot + 255) / 256, 256>>>(w_up, Ws, pwupT, pwT);
    }
    // 1) zero x_spe
    {
        int n4 = (NN * HH) / 4;
        zero_kernel<<<(n4 + 255) / 256, 256>>>((float4*)xspe, n4);
    }
    // 2) persistent per-layer tower (weights SMEM-resident)
    k_first<<<nsm, 512, F_SMEM>>>(x, rbf, idx, w_rbf, pwupT, xspe, pt0);
    layer_k<false><<<nsm, 512, M_SMEM>>>(pt0, pwT + 0 * DD * DD, bs + 0 * DD,
                                         nullptr, pt1, nullptr);
    layer_k<false><<<nsm, 512, M_SMEM>>>(pt1, pwT + 1 * DD * DD, bs + 1 * DD,
                                         nullptr, pt0, nullptr);
    layer_k<true><<<nsm, 512, M_SMEM>>>(pt0, pwT + 2 * DD * DD, bs + 2 * DD,
                                        w_out, nullptr, out1);
}

// round 10
// speedup vs baseline: 1.2085x; 1.2085x over previous
#include <cuda_runtime.h>
#include <cuda_fp16.h>
#include <math.h>
#include <stdint.h>

// Fixed problem shapes
#define EE 400000
#define NN 50000
#define RR 6
#define HH 128
#define DD 256

// Scratch
__device__ __half g_t1h[(size_t)EE * DD];       // fp16 intermediate t1
__device__ __half g_wupT[(size_t)DD * HH];      // w_up^T  [256][128] fp16
__device__ __half g_wT [(size_t)3 * DD * DD];   // Ws^T  3 x [256][256] fp16

// SMEM (halves): t strip 64 x 264, two weight stages 256 x 72
#define TSTR2 264
#define T_FL2 16896
#define WSTR2 72
#define WB_FL2 18432
#define SMEM_BYTES ((T_FL2 + 2 * WB_FL2) * 2)   // 107520

// ------------------------------------------------------------------
__device__ __forceinline__ uint32_t smem_u32(const void* p) {
    uint32_t a;
    asm("{ .reg .u64 t; cvta.to.shared.u64 t, %1; cvt.u32.u64 %0, t; }"
        : "=r"(a) : "l"(p));
    return a;
}
__device__ __forceinline__ void ldsm4(uint32_t& r0, uint32_t& r1,
                                      uint32_t& r2, uint32_t& r3,
                                      uint32_t addr) {
    asm volatile("ldmatrix.sync.aligned.m8n8.x4.shared.b16 {%0,%1,%2,%3}, [%4];"
                 : "=r"(r0), "=r"(r1), "=r"(r2), "=r"(r3) : "r"(addr));
}
__device__ __forceinline__ void mma_f16(float* c, const uint32_t* a,
                                        const uint32_t* b) {
    asm volatile(
        "mma.sync.aligned.m16n8k16.row.col.f32.f16.f16.f32 "
        "{%0,%1,%2,%3}, {%4,%5,%6,%7}, {%8,%9}, {%0,%1,%2,%3};"
        : "+f"(c[0]), "+f"(c[1]), "+f"(c[2]), "+f"(c[3])
        : "r"(a[0]), "r"(a[1]), "r"(a[2]), "r"(a[3]), "r"(b[0]), "r"(b[1]));
}
__device__ __forceinline__ float silu(float v) {
    return __fdividef(v, 1.f + __expf(-v));
}
// vectorized global float reduction (sm_90+): one instr for 4 atomic adds
__device__ __forceinline__ void red_add_v4(float* addr, float a, float b,
                                           float c, float d) {
    asm volatile("red.global.add.v4.f32 [%0], {%1, %2, %3, %4};"
                 :: "l"(addr), "f"(a), "f"(b), "f"(c), "f"(d) : "memory");
}
#define CP16(dst, src) \
    asm volatile("cp.async.cg.shared.global [%0], [%1], 16;" :: "r"(dst), "l"(src))
#define CPCOMMIT() asm volatile("cp.async.commit_group;" ::: "memory")
#define CPWAIT(n)  asm volatile("cp.async.wait_group %0;" :: "n"(n) : "memory")

// ------------------------------------------------------------------
__global__ void zero_kernel(float4* p, int n4) {
    int i = blockIdx.x * blockDim.x + threadIdx.x;
    if (i < n4) p[i] = make_float4(0.f, 0.f, 0.f, 0.f);
}

// transpose + fp16-convert weights: w_up^T then Ws^T
__global__ void convert_weights(const float* __restrict__ wup,
                                const float* __restrict__ Ws,
                                __half* __restrict__ wupT,
                                __half* __restrict__ wT) {
    int i = blockIdx.x * blockDim.x + threadIdx.x;
    if (i < DD * HH) {
        int n = i / HH, k = i % HH;
        wupT[i] = __float2half(wup[k * DD + n]);
        return;
    }
    i -= DD * HH;
    if (i < 3 * DD * DD) {
        int l = i / (DD * DD), r = i % (DD * DD);
        int n = r / DD, k = r % DD;
        wT[i] = __float2half(Ws[(size_t)l * DD * DD + k * DD + n]);
    }
}

// weight chunk: 256 n-rows x 64 k of WT[n][Kw] -> stage buffer
__device__ __forceinline__ void load_wchunk(uint32_t sbw, const __half* WT,
                                            int Kw, int k0) {
    const int tid = threadIdx.x;
#pragma unroll
    for (int it = 0; it < 8; it++) {
        int q = tid + it * 256;
        int row = q >> 3, seg = q & 7;
        uint32_t dst = sbw + (uint32_t)(row * WSTR2 + seg * 8) * 2;
        CP16(dst, WT + (size_t)row * Kw + k0 + seg * 8);
    }
}

// ------------------------------------------------------------------
// One fp16 layer on the resident 64-row strip: acc = t[:,0:KTOT] @ WT^T.
// Entry: W chunk0 issued+committed in stage0. Exit: nextWT chunk0 prefetched.
template<int KTOT, bool ACT, bool LAST>
__device__ __forceinline__ void gemm_layer(
    __half* smh, uint32_t sbt, const __half* WT, const __half* nextWT,
    int nextKw, const float* __restrict__ bias, const float* __restrict__ wout,
    __half* __restrict__ Cg, float* __restrict__ out1, size_t e0)
{
    constexpr int NCH = KTOT / 64;
    const int tid = threadIdx.x;
    const int wn = tid >> 5, lane = tid & 31;
    const int g = lane >> 2, t = lane & 3;

    // ldmatrix lane address components
    const int arow = lane & 15;
    const int acol = (lane & 16) ? 8 : 0;
    const uint32_t a_base = sbt + (uint32_t)(arow * TSTR2 + acol) * 2;
    const int brow = (lane & 7) + ((lane & 16) ? 8 : 0);
    const int bcol = (lane & 8) ? 8 : 0;
    const uint32_t b_lane = (uint32_t)((wn * 32 + brow) * WSTR2 + bcol) * 2;

    float acc[4][4][4];
#pragma unroll
    for (int i = 0; i < 4; i++)
#pragma unroll
        for (int j = 0; j < 4; j++)
#pragma unroll
            for (int q = 0; q < 4; q++) acc[i][j][q] = 0.f;

#pragma unroll 1
    for (int c = 0; c < NCH; c++) {
        if (c + 1 < NCH) {
            load_wchunk(sbt + (uint32_t)(T_FL2 + ((c + 1) & 1) * WB_FL2) * 2,
                        WT, KTOT, (c + 1) * 64);
            CPCOMMIT();
            CPWAIT(1);
        } else {
            CPWAIT(0);
        }
        __syncthreads();
        const uint32_t sbw = sbt + (uint32_t)(T_FL2 + (c & 1) * WB_FL2) * 2;
#pragma unroll
        for (int ks = 0; ks < 4; ks++) {
            uint32_t af[4][4], bf[4][2];
            const uint32_t ak = (uint32_t)(c * 64 + ks * 16) * 2;
#pragma unroll
            for (int mf = 0; mf < 4; mf++)
                ldsm4(af[mf][0], af[mf][1], af[mf][2], af[mf][3],
                      a_base + ak + (uint32_t)(mf * 16 * TSTR2) * 2);
            const uint32_t bk = (uint32_t)(ks * 16) * 2;
#pragma unroll
            for (int np = 0; np < 2; np++) {
                uint32_t d0, d1, d2, d3;
                ldsm4(d0, d1, d2, d3,
                      sbw + b_lane + bk + (uint32_t)(np * 16 * WSTR2) * 2);
                bf[2 * np][0] = d0;  bf[2 * np][1] = d1;
                bf[2 * np + 1][0] = d2;  bf[2 * np + 1][1] = d3;
            }
#pragma unroll
            for (int mf = 0; mf < 4; mf++)
#pragma unroll
                for (int nf = 0; nf < 4; nf++)
                    mma_f16(acc[mf][nf], af[mf], bf[nf]);
        }
        __syncthreads();
    }

    if (nextWT) {                      // prefetch next layer chunk0 (stage 0)
        load_wchunk(sbt + (uint32_t)T_FL2 * 2, nextWT, nextKw, 0);
        CPCOMMIT();
    }

    if (!LAST) {
#pragma unroll
        for (int mf = 0; mf < 4; mf++) {
#pragma unroll
            for (int nf = 0; nf < 4; nf++) {
                int r0 = mf * 16 + g;
                int cc = wn * 32 + nf * 8 + 2 * t;
                float v0 = acc[mf][nf][0], v1 = acc[mf][nf][1];
                float v2 = acc[mf][nf][2], v3 = acc[mf][nf][3];
                if (ACT) {
                    float b0 = __ldg(bias + cc), b1 = __ldg(bias + cc + 1);
                    v0 = silu(v0 + b0); v1 = silu(v1 + b1);
                    v2 = silu(v2 + b0); v3 = silu(v3 + b1);
                }
                __half2 h01 = __floats2half2_rn(v0, v1);
                __half2 h23 = __floats2half2_rn(v2, v3);
                if (Cg) {
                    *reinterpret_cast<__half2*>(Cg + (e0 + r0) * DD + cc) = h01;
                    *reinterpret_cast<__half2*>(Cg + (e0 + r0 + 8) * DD + cc) = h23;
                } else {
                    *reinterpret_cast<__half2*>(smh + r0 * TSTR2 + cc) = h01;
                    *reinterpret_cast<__half2*>(smh + (r0 + 8) * TSTR2 + cc) = h23;
                }
            }
        }
        __syncthreads();
    } else {
        float s0[4], s1[4];
#pragma unroll
        for (int mf = 0; mf < 4; mf++) { s0[mf] = 0.f; s1[mf] = 0.f; }
#pragma unroll
        for (int mf = 0; mf < 4; mf++) {
#pragma unroll
            for (int nf = 0; nf < 4; nf++) {
                int cc = wn * 32 + nf * 8 + 2 * t;
                float b0 = __ldg(bias + cc), b1 = __ldg(bias + cc + 1);
                float w0 = __ldg(wout + cc), w1 = __ldg(wout + cc + 1);
                s0[mf] += silu(acc[mf][nf][0] + b0) * w0
                        + silu(acc[mf][nf][1] + b1) * w1;
                s1[mf] += silu(acc[mf][nf][2] + b0) * w0
                        + silu(acc[mf][nf][3] + b1) * w1;
            }
        }
#pragma unroll
        for (int mf = 0; mf < 4; mf++) {
            s0[mf] += __shfl_xor_sync(0xffffffffu, s0[mf], 1);
            s0[mf] += __shfl_xor_sync(0xffffffffu, s0[mf], 2);
            s1[mf] += __shfl_xor_sync(0xffffffffu, s1[mf], 1);
            s1[mf] += __shfl_xor_sync(0xffffffffu, s1[mf], 2);
        }
        float* red = reinterpret_cast<float*>(smh + T_FL2);
        if (t == 0) {
#pragma unroll
            for (int mf = 0; mf < 4; mf++) {
                red[(mf * 16 + g) * 8 + wn] = s0[mf];
                red[(mf * 16 + 8 + g) * 8 + wn] = s1[mf];
            }
        }
        __syncthreads();
        if (tid < 64) {
            float s = 0.f;
#pragma unroll
            for (int j = 0; j < 8; j++) s += red[tid * 8 + j];
            out1[e0 + tid] = s;
        }
    }
}

// ------------------------------------------------------------------
// K1: h = (rbf@w_rbf)*x (fp32 vectorized red scatter, fp16 strip)
//     -> W_up -> W0+silu -> t1
__global__ __launch_bounds__(256, 2)
void tower_k1(const float* __restrict__ x,  const float* __restrict__ rbf,
              const int*   __restrict__ idx, const float* __restrict__ w_rbf,
              const __half* __restrict__ wupT, const __half* __restrict__ wT,
              const float* __restrict__ bs,
              float* __restrict__ xspe, __half* __restrict__ t1)
{
    extern __shared__ __half smh[];
    const uint32_t sbt = smem_u32(smh);
    const int tid = threadIdx.x;
    const size_t e0 = (size_t)blockIdx.x * 64;

    // prefetch W_up chunk0
    load_wchunk(sbt + (uint32_t)T_FL2 * 2, wupT, HH, 0);
    CPCOMMIT();

    // h phase: row r = tid/4, cols (tid%4)*32 .. +31
    {
        const int r = tid >> 2;
        const int cg = (tid & 3) << 5;
        const float* xb = x + (e0 + r) * HH;
        const float* rb = rbf + (e0 + r) * RR;
        float r0 = __ldg(rb + 0), r1 = __ldg(rb + 1), r2 = __ldg(rb + 2);
        float r3 = __ldg(rb + 3), r4 = __ldg(rb + 4), r5 = __ldg(rb + 5);
        const int node = __ldg(idx + e0 + r);
        __half* trow = smh + r * TSTR2;
        float* xd = xspe + (size_t)node * HH;
#pragma unroll
        for (int cc = 0; cc < 32; cc += 4) {
            int c = cg + cc;
            float4 xv = __ldg((const float4*)(xb + c));
            float4 w0 = __ldg((const float4*)(w_rbf + 0 * HH + c));
            float4 w1 = __ldg((const float4*)(w_rbf + 1 * HH + c));
            float4 w2 = __ldg((const float4*)(w_rbf + 2 * HH + c));
            float4 w3 = __ldg((const float4*)(w_rbf + 3 * HH + c));
            float4 w4 = __ldg((const float4*)(w_rbf + 4 * HH + c));
            float4 w5 = __ldg((const float4*)(w_rbf + 5 * HH + c));
            float4 h;
            h.x = (r0*w0.x + r1*w1.x + r2*w2.x + r3*w3.x + r4*w4.x + r5*w5.x) * xv.x;
            h.y = (r0*w0.y + r1*w1.y + r2*w2.y + r3*w3.y + r4*w4.y + r5*w5.y) * xv.y;
            h.z = (r0*w0.z + r1*w1.z + r2*w2.z + r3*w3.z + r4*w4.z + r5*w5.z) * xv.z;
            h.w = (r0*w0.w + r1*w1.w + r2*w2.w + r3*w3.w + r4*w4.w + r5*w5.w) * xv.w;
            *reinterpret_cast<__half2*>(trow + c)     = __floats2half2_rn(h.x, h.y);
            *reinterpret_cast<__half2*>(trow + c + 2) = __floats2half2_rn(h.z, h.w);
            red_add_v4(xd + c, h.x, h.y, h.z, h.w);
        }
    }
    __syncthreads();

    gemm_layer<128, false, false>(smh, sbt, wupT, wT, DD,
                                  nullptr, nullptr, nullptr, nullptr, e0);
    gemm_layer<256, true, false>(smh, sbt, wT, nullptr, 0,
                                 bs + 0 * DD, nullptr, t1, nullptr, e0);
}

// K2: t1 strip -> W1+silu -> W2 + silu.w_out -> out1
__global__ __launch_bounds__(256, 2)
void tower_k2(const __half* __restrict__ t1, const __half* __restrict__ wT,
              const float* __restrict__ bs, const float* __restrict__ wout,
              float* __restrict__ out1)
{
    extern __shared__ __half smh[];
    const uint32_t sbt = smem_u32(smh);
    const int tid = threadIdx.x;
    const size_t e0 = (size_t)blockIdx.x * 64;

    const __half* W1 = wT + 1 * DD * DD;
    const __half* W2 = wT + 2 * DD * DD;

    // t1 strip 64 x 256 fp16
#pragma unroll
    for (int it = 0; it < 8; it++) {
        int q = tid + it * 256;
        int row = q >> 5, seg = q & 31;
        CP16(sbt + (uint32_t)(row * TSTR2 + seg * 8) * 2,
             t1 + (e0 + row) * DD + seg * 8);
    }
    CPCOMMIT();
    load_wchunk(sbt + (uint32_t)T_FL2 * 2, W1, DD, 0);
    CPCOMMIT();
    CPWAIT(1);          // t strip landed
    __syncthreads();

    gemm_layer<256, true, false>(smh, sbt, W1, W2, DD,
                                 bs + 1 * DD, nullptr, nullptr, nullptr, e0);
    gemm_layer<256, true, true>(smh, sbt, W2, nullptr, 0,
                                bs + 2 * DD, wout, nullptr, out1, e0);
}

// ------------------------------------------------------------------
extern "C" void kernel_launch(void* const* d_in, const int* in_sizes, int n_in,
                              void* d_out, int out_size) {
    const float* x     = (const float*)d_in[0];
    const float* rbf   = (const float*)d_in[1];
    const int*   idx   = (const int*)  d_in[2];
    const float* w_rbf = (const float*)d_in[3];
    const float* w_up  = (const float*)d_in[4];
    const float* Ws    = (const float*)d_in[5];
    const float* bs    = (const float*)d_in[6];
    const float* w_out = (const float*)d_in[7];

    const int E = in_sizes[2];                    // 400000

    float* out_f = (float*)d_out;
    float* xspe  = out_f;                         // [N,128]
    float* out1  = out_f + (size_t)NN * HH;       // [E]

    __half *pt1, *pwupT, *pwT;
    cudaGetSymbolAddress((void**)&pt1,   g_t1h);
    cudaGetSymbolAddress((void**)&pwupT, g_wupT);
    cudaGetSymbolAddress((void**)&pwT,   g_wT);

    cudaFuncSetAttribute(tower_k1,
                         cudaFuncAttributeMaxDynamicSharedMemorySize, SMEM_BYTES);
    cudaFuncSetAttribute(tower_k2,
                         cudaFuncAttributeMaxDynamicSharedMemorySize, SMEM_BYTES);

    // 0) transpose + convert weights to fp16
    {
        int tot = DD * HH + 3 * DD * DD;
        convert_weights<<<(tot + 255) / 256, 256>>>(w_up, Ws, pwupT, pwT);
    }
    // 1) zero x_spe (out1 fully written by K2)
    {
        int n4 = (NN * HH) / 4;
        zero_kernel<<<(n4 + 255) / 256, 256>>>((float4*)xspe, n4);
    }
    // 2) pairwise-fused fp16 tensor-core tower
    {
        int grid = E / 64;                        // 6250
        tower_k1<<<grid, 256, SMEM_BYTES>>>(x, rbf, idx, w_rbf, pwupT, pwT,
                                            bs, xspe, pt1);
        tower_k2<<<grid, 256, SMEM_BYTES>>>(pt1, pwT, bs, w_out, out1);
    }
}